// round 14
// baseline (speedup 1.0000x reference)
#include <cuda_runtime.h>
#include <cuda_bf16.h>
#include <math.h>
#include <stdint.h>

// Problem constants
#define BB   4
#define SS   2048
#define DD   768
#define HH   12
#define HDD  64
#define FF   3072
#define ROWS (BB*SS)   // 8192
#define NC   2304      // 3*DD packed qkv cols

// ---------------- scratch (device globals; no runtime allocation) ----------
__device__ float g_part[3*(size_t)ROWS*DD];      // split-K fp32 partials (3 planes)
__device__ float g_bp [NC];                      // packed QKV bias
__device__ __align__(256) __nv_bfloat16 g_h_hi[ROWS*DD], g_h_lo[ROWS*DD];
__device__ __align__(256) __nv_bfloat16 g_qkvh[ROWS*NC], g_qkvl[ROWS*NC];   // split qkv
__device__ __align__(256) __nv_bfloat16 g_o_hi[ROWS*DD], g_o_lo[ROWS*DD];
__device__ __align__(256) __nv_bfloat16 g_f_hi[ROWS*FF], g_f_lo[ROWS*FF];
__device__ __align__(256) __nv_bfloat16 g_Wqkv_hi[NC*DD], g_Wqkv_lo[NC*DD]; // [2304][768]
__device__ __align__(256) __nv_bfloat16 g_Wo_hi[DD*DD],  g_Wo_lo[DD*DD];    // [768][768]
__device__ __align__(256) __nv_bfloat16 g_W1_hi[FF*DD],  g_W1_lo[FF*DD];    // [3072][768]
__device__ __align__(256) __nv_bfloat16 g_W2_hi[DD*FF],  g_W2_lo[DD*FF];    // [768][3072]

// ================= PTX helpers (baseline ISA only: sm_80-class) =============
__device__ __forceinline__ uint32_t smem_u32(const void* p) {
    uint32_t a;
    asm("{ .reg .u64 t; cvta.to.shared.u64 t, %1; cvt.u32.u64 %0, t; }" : "=r"(a) : "l"(p));
    return a;
}
#define CP16(dst, src) asm volatile("cp.async.cg.shared.global [%0], [%1], 16;" :: "r"(dst), "l"(src))
#define CP_COMMIT()    asm volatile("cp.async.commit_group;" ::: "memory")
#define CP_WAIT(n)     asm volatile("cp.async.wait_group %0;" :: "n"(n) : "memory")

#define LDM4(r, addr) \
    asm volatile("ldmatrix.sync.aligned.m8n8.x4.shared.b16 {%0,%1,%2,%3}, [%4];" \
        : "=r"((r)[0]), "=r"((r)[1]), "=r"((r)[2]), "=r"((r)[3]) : "r"(addr))
#define LDM4T(r, addr) \
    asm volatile("ldmatrix.sync.aligned.m8n8.x4.trans.shared.b16 {%0,%1,%2,%3}, [%4];" \
        : "=r"((r)[0]), "=r"((r)[1]), "=r"((r)[2]), "=r"((r)[3]) : "r"(addr))

#define MMA16816(d, a, b0v, b1v) \
    asm volatile("mma.sync.aligned.m16n8k16.row.col.f32.bf16.bf16.f32 " \
        "{%0,%1,%2,%3},{%4,%5,%6,%7},{%8,%9},{%0,%1,%2,%3};" \
        : "+f"((d)[0]), "+f"((d)[1]), "+f"((d)[2]), "+f"((d)[3]) \
        : "r"((a)[0]), "r"((a)[1]), "r"((a)[2]), "r"((a)[3]), "r"(b0v), "r"(b1v))

__device__ __forceinline__ void split_bf16(float v, __nv_bfloat16& hi, __nv_bfloat16& lo) {
    hi = __float2bfloat16(v);
    lo = __float2bfloat16(v - __bfloat162float(hi));
}
__device__ __forceinline__ uint32_t pack_bf2(float a, float b) {
    __nv_bfloat162 t = __halves2bfloat162(__float2bfloat16(a), __float2bfloat16(b));
    return *(uint32_t*)&t;
}
__device__ __forceinline__ float gelu_exact(float x) {
    return 0.5f * x * (1.0f + erff(x * 0.70710678118654752f));
}

// ================= weight conversion (coalesced transposes) =================
// W[K][N] fp32 -> O[N][K] split bf16, 32x32 smem tiles.
__global__ void tcvt_t(const float* __restrict__ W, __nv_bfloat16* __restrict__ Ohi,
                       __nv_bfloat16* __restrict__ Olo, int K, int N)
{
    __shared__ float t[32][33];
    int n0 = blockIdx.x * 32, k0 = blockIdx.y * 32;
    int tx = threadIdx.x, ty = threadIdx.y;
    #pragma unroll
    for (int j = 0; j < 4; j++)
        t[ty + 8 * j][tx] = W[(size_t)(k0 + ty + 8 * j) * N + n0 + tx];
    __syncthreads();
    #pragma unroll
    for (int j = 0; j < 4; j++) {
        int n = n0 + ty + 8 * j;
        float v = t[tx][ty + 8 * j];
        __nv_bfloat16 hi, lo; split_bf16(v, hi, lo);
        Ohi[(size_t)n * K + k0 + tx] = hi;
        Olo[(size_t)n * K + k0 + tx] = lo;
    }
}
// Wq/Wk/Wv [H][D][HD] -> g_Wqkv[(part*768+h*64+e)][d], transposed per (part,h)
__global__ void qkv_cvt_t(const float* __restrict__ Wq, const float* __restrict__ Wk,
                          const float* __restrict__ Wv)
{
    __shared__ float t[32][33];
    int d0 = blockIdx.x * 32, e0 = blockIdx.y * 32;
    int part = blockIdx.z / HH, h = blockIdx.z % HH;
    const float* W = (part == 0) ? Wq : (part == 1) ? Wk : Wv;
    int tx = threadIdx.x, ty = threadIdx.y;
    #pragma unroll
    for (int j = 0; j < 4; j++)
        t[ty + 8 * j][tx] = W[(size_t)(h * DD + d0 + ty + 8 * j) * HDD + e0 + tx];
    __syncthreads();
    #pragma unroll
    for (int j = 0; j < 4; j++) {
        int e = e0 + ty + 8 * j;
        int row = part * DD + h * HDD + e;
        float v = t[tx][ty + 8 * j];
        __nv_bfloat16 hi, lo; split_bf16(v, hi, lo);
        g_Wqkv_hi[(size_t)row * DD + d0 + tx] = hi;
        g_Wqkv_lo[(size_t)row * DD + d0 + tx] = lo;
    }
}
__global__ void qkv_bias(const float* __restrict__ bq, const float* __restrict__ bk,
                         const float* __restrict__ bv)
{
    int j = blockIdx.x * 256 + threadIdx.x;
    if (j >= NC) return;
    int part = j / DD, jj = j - part * DD;
    const float* bb = (part == 0) ? bq : (part == 1) ? bk : bv;
    g_bp[j] = bb[jj];
}

// ================= layer norm (writes split bf16) =================
__global__ void ln_kernel(const float* __restrict__ x, const float* __restrict__ g,
                          const float* __restrict__ b, __nv_bfloat16* __restrict__ yhi,
                          __nv_bfloat16* __restrict__ ylo)
{
    int row = blockIdx.x;
    int tid = threadIdx.x;
    const float* xr = x + (size_t)row * DD;
    float v0 = xr[tid], v1 = xr[tid + 256], v2 = xr[tid + 512];
    float s  = v0 + v1 + v2;
    float ss = v0 * v0 + v1 * v1 + v2 * v2;
    #pragma unroll
    for (int o = 16; o >= 1; o >>= 1) {
        s  += __shfl_xor_sync(0xffffffffu, s,  o);
        ss += __shfl_xor_sync(0xffffffffu, ss, o);
    }
    __shared__ float rs[8], rss[8];
    int w = tid >> 5, l = tid & 31;
    if (l == 0) { rs[w] = s; rss[w] = ss; }
    __syncthreads();
    float S = 0.f, S2 = 0.f;
    #pragma unroll
    for (int i = 0; i < 8; i++) { S += rs[i]; S2 += rss[i]; }
    float mu  = S  * (1.0f / DD);
    float var = S2 * (1.0f / DD) - mu * mu;
    float inv = rsqrtf(var + 1e-5f);
    #pragma unroll
    for (int q = 0; q < 3; q++) {
        int c = tid + q * 256;
        float v = (q == 0 ? v0 : q == 1 ? v1 : v2);
        float y = (v - mu) * inv * g[c] + b[c];
        __nv_bfloat16 hi, lo; split_bf16(y, hi, lo);
        yhi[(size_t)row * DD + c] = hi;
        ylo[(size_t)row * DD + c] = lo;
    }
}

// LN2 fused over 3 split-K partials + bias (a = sum + bo; y = LN(a) -> split)
__global__ void ln2_fuse(const float* __restrict__ bo, const float* __restrict__ g,
                         const float* __restrict__ b, __nv_bfloat16* __restrict__ yhi,
                         __nv_bfloat16* __restrict__ ylo)
{
    const size_t plane = (size_t)ROWS * DD;
    int row = blockIdx.x;
    int tid = threadIdx.x;
    const float* p = g_part + (size_t)row * DD;
    float v[3];
    #pragma unroll
    for (int q = 0; q < 3; q++) {
        int c = tid + q * 256;
        v[q] = p[c] + p[plane + c] + p[2 * plane + c] + bo[c];
    }
    float s  = v[0] + v[1] + v[2];
    float ss = v[0]*v[0] + v[1]*v[1] + v[2]*v[2];
    #pragma unroll
    for (int o = 16; o >= 1; o >>= 1) {
        s  += __shfl_xor_sync(0xffffffffu, s,  o);
        ss += __shfl_xor_sync(0xffffffffu, ss, o);
    }
    __shared__ float rs[8], rss[8];
    int w = tid >> 5, l = tid & 31;
    if (l == 0) { rs[w] = s; rss[w] = ss; }
    __syncthreads();
    float S = 0.f, S2 = 0.f;
    #pragma unroll
    for (int i = 0; i < 8; i++) { S += rs[i]; S2 += rss[i]; }
    float mu  = S  * (1.0f / DD);
    float var = S2 * (1.0f / DD) - mu * mu;
    float inv = rsqrtf(var + 1e-5f);
    #pragma unroll
    for (int q = 0; q < 3; q++) {
        int c = tid + q * 256;
        float y = (v[q] - mu) * inv * g[c] + b[c];
        __nv_bfloat16 hi, lo; split_bf16(y, hi, lo);
        yhi[(size_t)row * DD + c] = hi;
        ylo[(size_t)row * DD + c] = lo;
    }
}

// out = p0 + p1 + p2 + bias (FFN2 reduce)
__global__ void addbias3(const float* __restrict__ bias, float* __restrict__ out)
{
    const size_t plane = (size_t)ROWS * DD;
    size_t i4 = ((size_t)blockIdx.x * 256 + threadIdx.x) * 4;
    if (i4 >= plane) return;
    int c = (int)(i4 % DD);
    float4 a = *(const float4*)(g_part + i4);
    float4 b = *(const float4*)(g_part + plane + i4);
    float4 d = *(const float4*)(g_part + 2 * plane + i4);
    float4 bb = *(const float4*)(bias + c);
    float4 r;
    r.x = a.x + b.x + d.x + bb.x;
    r.y = a.y + b.y + d.y + bb.y;
    r.z = a.z + b.z + d.z + bb.z;
    r.w = a.w + b.w + d.w + bb.w;
    *(float4*)(out + i4) = r;
}

// ================ mma.sync GEMM: C[M,N] = A[M,K] @ Bt[N,K]^T ================
// 4 warps (2x2 grid), 64x64 warp tile, 128 threads, 2 CTAs/SM.
// Warp-tile 64x64 raises MMA/ldmatrix ratio 4 -> 6 (33% less smem-crossbar
// traffic, the R12-identified bottleneck). Single-barrier 3-stage pipeline
// with loads issued before compute (R12-validated).
#define STAGE_B  32768
#define GEMM_SMEM (3*STAGE_B)

template<int ACT, int OSPLIT, int PART>
__global__ __launch_bounds__(128, 2)
void tgemm(const __nv_bfloat16* __restrict__ Ahi, const __nv_bfloat16* __restrict__ Alo,
           const __nv_bfloat16* __restrict__ Bhi, const __nv_bfloat16* __restrict__ Blo,
           const float* __restrict__ bias,
           float* __restrict__ Cf, __nv_bfloat16* __restrict__ Chi,
           __nv_bfloat16* __restrict__ Clo, int N, int K)
{
    extern __shared__ char smem[];
    uint32_t ST = smem_u32(smem);
    int tid = threadIdx.x;
    int lane = tid & 31, wid = tid >> 5;
    int wm = wid & 1, wn = wid >> 1;          // warp grid 2 x 2, tile 64x64
    int m0 = blockIdx.y * 128;
    int n0 = blockIdx.x * 128;
    int KH = PART ? (K / (int)gridDim.z) : K;
    int koff = PART ? ((int)blockIdx.z * KH) : 0;
    int nc = KH >> 5;                          // K chunks of 32

    const __nv_bfloat16* Abase_h = Ahi + (size_t)m0 * K + koff;
    const __nv_bfloat16* Abase_l = Alo + (size_t)m0 * K + koff;
    const __nv_bfloat16* Bbase_h = Bhi + (size_t)n0 * K + koff;
    const __nv_bfloat16* Bbase_l = Blo + (size_t)n0 * K + koff;

    auto load_chunk = [&](int c, int p) {
        uint32_t base = ST + p * STAGE_B;
        const __nv_bfloat16* ah = Abase_h + c * 32;
        const __nv_bfloat16* al = Abase_l + c * 32;
        const __nv_bfloat16* bh = Bbase_h + c * 32;
        const __nv_bfloat16* bl = Bbase_l + c * 32;
        #pragma unroll
        for (int j = 0; j < 4; j++) {
            int id = tid + 128 * j;            // 0..511 : 128 rows x 4 chunks
            int r = id >> 2, cc = id & 3;
            uint32_t off = (uint32_t)(r * 64 + ((cc ^ ((r >> 1) & 3)) << 4));
            const size_t go = (size_t)r * K + cc * 8;
            CP16(base +         off, ah + go);
            CP16(base +  8192 + off, al + go);
            CP16(base + 16384 + off, bh + go);
            CP16(base + 24576 + off, bl + go);
        }
    };

    float acc[4][8][4];
    #pragma unroll
    for (int s = 0; s < 4; s++)
        #pragma unroll
        for (int t = 0; t < 8; t++)
            #pragma unroll
            for (int q = 0; q < 4; q++) acc[s][t][q] = 0.f;

    load_chunk(0, 0); CP_COMMIT();
    load_chunk(1, 1); CP_COMMIT();

    int arow = wm * 64 + (lane & 15);         // + sub*16
    int brow = wn * 64 + (lane & 15);         // + nh*16
    int khalf = lane >> 4;

    for (int c = 0; c < nc; c++) {
        CP_WAIT(1);                 // chunk c landed (next group may be in flight)
        __syncthreads();            // all warps past iter c-1 (stage (c+2)%3 free)
        if (c + 2 < nc) load_chunk(c + 2, (c + 2) % 3);
        CP_COMMIT();                // empty when skipped: uniform group count
        uint32_t base = ST + (c % 3) * STAGE_B;
        uint32_t Ah = base, Al = base + 8192, Bh = base + 16384, Bl = base + 24576;
        #pragma unroll
        for (int ks = 0; ks < 2; ks++) {
            int kc = ks * 2 + khalf;
            uint32_t ahf[4][4], alf[4][4];
            #pragma unroll
            for (int sub = 0; sub < 4; sub++) {
                int r = arow + sub * 16;
                uint32_t off = (uint32_t)(r * 64 + ((kc ^ ((r >> 1) & 3)) << 4));
                LDM4(ahf[sub], Ah + off);
                LDM4(alf[sub], Al + off);
            }
            #pragma unroll
            for (int nh = 0; nh < 4; nh++) {
                int n = brow + nh * 16;
                uint32_t off = (uint32_t)(n * 64 + ((kc ^ ((n >> 1) & 3)) << 4));
                uint32_t bhf[4], blf[4];
                LDM4(bhf, Bh + off);
                LDM4(blf, Bl + off);
                #pragma unroll
                for (int sub = 0; sub < 4; sub++) {
                    #pragma unroll
                    for (int nt = 0; nt < 2; nt++) {
                        float* d = acc[sub][nh * 2 + nt];
                        MMA16816(d, ahf[sub], bhf[nt], bhf[nt + 2]);
                        MMA16816(d, ahf[sub], blf[nt], blf[nt + 2]);
                        MMA16816(d, alf[sub], bhf[nt], bhf[nt + 2]);
                    }
                }
            }
        }
    }

    // ---------------- epilogue ----------------
    float* Cpart = PART ? (Cf + (size_t)blockIdx.z * ROWS * N) : Cf;
    int g = lane >> 2, t = lane & 3;
    #pragma unroll
    for (int sub = 0; sub < 4; sub++) {
        #pragma unroll
        for (int nt8 = 0; nt8 < 8; nt8++) {
            int col = n0 + wn * 64 + nt8 * 8 + t * 2;
            float b0 = PART ? 0.f : bias[col];
            float b1 = PART ? 0.f : bias[col + 1];
            #pragma unroll
            for (int half = 0; half < 2; half++) {
                int row = m0 + wm * 64 + sub * 16 + g + half * 8;
                float v0 = acc[sub][nt8][half * 2 + 0] + b0;
                float v1 = acc[sub][nt8][half * 2 + 1] + b1;
                if (ACT) { v0 = gelu_exact(v0); v1 = gelu_exact(v1); }
                if (OSPLIT) {
                    __nv_bfloat16 h0, l0, h1, l1;
                    split_bf16(v0, h0, l0); split_bf16(v1, h1, l1);
                    *(__nv_bfloat162*)(Chi + (size_t)row * N + col) = __halves2bfloat162(h0, h1);
                    *(__nv_bfloat162*)(Clo + (size_t)row * N + col) = __halves2bfloat162(l0, l1);
                } else {
                    float2 fv; fv.x = v0; fv.y = v1;
                    *(float2*)(Cpart + (size_t)row * N + col) = fv;
                }
            }
        }
    }
}

// ============ tensor-core flash attention (bf16 split, 64x64 tiles) =========
// R10/R12-validated config: 64-row Q tile, 128 threads, 2 CTAs/SM, 3-stage KV
// pipeline with loads issued before compute. UNCHANGED this round.
#define ATT_STAGE 32768
#define ATT_SMEM  (16384 + 3*ATT_STAGE)

__device__ __forceinline__ uint32_t aoff(int r, int c) {
    return (uint32_t)((r << 7) + (((c ^ (r & 7)) & 7) << 4));
}

__global__ __launch_bounds__(128, 2)
void attn_tc(const __nv_bfloat16* __restrict__ qh, const __nv_bfloat16* __restrict__ ql,
             __nv_bfloat16* __restrict__ ohi, __nv_bfloat16* __restrict__ olo)
{
    extern __shared__ char sm[];
    uint32_t S0 = smem_u32(sm);
    const uint32_t Qh = S0, Ql = S0 + 8192;
    int tid = threadIdx.x, lane = tid & 31, wid = tid >> 5;
    int bh = blockIdx.y, b = bh / HH, h = bh - b * HH;
    int q0 = blockIdx.x * 64;
    size_t rowbase = (size_t)b * SS * NC + h * 64;
    const int NT = SS / 64;

    {
        const __nv_bfloat16* qph = qh + rowbase + (size_t)q0 * NC;
        const __nv_bfloat16* qpl = ql + rowbase + (size_t)q0 * NC;
        #pragma unroll
        for (int j = 0; j < 4; j++) {
            int id = tid + 128 * j; int r = id >> 3, c = id & 7;
            size_t go = (size_t)r * NC + c * 8;
            CP16(Qh + aoff(r, c), qph + go);
            CP16(Ql + aoff(r, c), qpl + go);
        }
        CP_COMMIT();
    }
    auto load_kv = [&](int kt, int p) {
        uint32_t base = S0 + 16384 + p * ATT_STAGE;
        size_t kb = rowbase + (size_t)(kt * 64) * NC + 768;
        size_t vb = kb + 768;
        #pragma unroll
        for (int j = 0; j < 4; j++) {
            int id = tid + 128 * j; int r = id >> 3, c = id & 7;
            uint32_t o_ = aoff(r, c);
            size_t go = (size_t)r * NC + c * 8;
            CP16(base +         o_, qh + kb + go);
            CP16(base +  8192 + o_, ql + kb + go);
            CP16(base + 16384 + o_, qh + vb + go);
            CP16(base + 24576 + o_, ql + vb + go);
        }
    };
    load_kv(0, 0); CP_COMMIT();
    load_kv(1, 1); CP_COMMIT();

    float o[8][4];
    #pragma unroll
    for (int i = 0; i < 8; i++)
        #pragma unroll
        for (int q = 0; q < 4; q++) o[i][q] = 0.f;
    float m0r = -1e30f, m1r = -1e30f, l0r = 0.f, l1r = 0.f;
    int g = lane >> 2, t = lane & 3;
    int arow = wid * 16 + (lane & 15);
    int khalf = lane >> 4;

    for (int kt = 0; kt < NT; kt++) {
        int p = kt % 3;
        CP_WAIT(1);
        __syncthreads();
        if (kt + 2 < NT) load_kv(kt + 2, (kt + 2) % 3);
        CP_COMMIT();
        uint32_t base = S0 + 16384 + p * ATT_STAGE;
        uint32_t Kh = base, Kl = base + 8192, Vh = base + 16384, Vl = base + 24576;

        float s[8][4];
        #pragma unroll
        for (int i = 0; i < 8; i++)
            #pragma unroll
            for (int q = 0; q < 4; q++) s[i][q] = 0.f;
        #pragma unroll
        for (int ks = 0; ks < 4; ks++) {
            uint32_t qah[4], qal[4];
            uint32_t ao = aoff(arow, ks * 2 + khalf);
            LDM4(qah, Qh + ao);
            LDM4(qal, Ql + ao);
            #pragma unroll
            for (int np = 0; np < 4; np++) {
                uint32_t bo = aoff(np * 16 + (lane & 15), ks * 2 + khalf);
                uint32_t kbh[4], kbl[4];
                LDM4(kbh, Kh + bo);
                LDM4(kbl, Kl + bo);
                #pragma unroll
                for (int half = 0; half < 2; half++) {
                    float* d = s[np * 2 + half];
                    MMA16816(d, qah, kbh[half], kbh[half + 2]);
                    MMA16816(d, qah, kbl[half], kbl[half + 2]);
                    MMA16816(d, qal, kbh[half], kbh[half + 2]);
                }
            }
        }
        float mn0 = m0r, mn1 = m1r;
        #pragma unroll
        for (int nb = 0; nb < 8; nb++) {
            s[nb][0] *= 0.125f; s[nb][1] *= 0.125f;
            s[nb][2] *= 0.125f; s[nb][3] *= 0.125f;
            mn0 = fmaxf(mn0, fmaxf(s[nb][0], s[nb][1]));
            mn1 = fmaxf(mn1, fmaxf(s[nb][2], s[nb][3]));
        }
        mn0 = fmaxf(mn0, __shfl_xor_sync(0xffffffffu, mn0, 1));
        mn0 = fmaxf(mn0, __shfl_xor_sync(0xffffffffu, mn0, 2));
        mn1 = fmaxf(mn1, __shfl_xor_sync(0xffffffffu, mn1, 1));
        mn1 = fmaxf(mn1, __shfl_xor_sync(0xffffffffu, mn1, 2));
        float al0 = __expf(m0r - mn0), al1 = __expf(m1r - mn1);
        m0r = mn0; m1r = mn1;
        float sum0 = 0.f, sum1 = 0.f;
        uint32_t ph[4][4], pl[4][4];
        #pragma unroll
        for (int kg = 0; kg < 4; kg++) {
            #pragma unroll
            for (int half = 0; half < 2; half++) {
                int nb = kg * 2 + half;
                float p0 = __expf(s[nb][0] - mn0), p1 = __expf(s[nb][1] - mn0);
                float p2 = __expf(s[nb][2] - mn1), p3 = __expf(s[nb][3] - mn1);
                sum0 += p0 + p1; sum1 += p2 + p3;
                float h0 = __bfloat162float(__float2bfloat16(p0));
                float h1 = __bfloat162float(__float2bfloat16(p1));
                float h2 = __bfloat162float(__float2bfloat16(p2));
                float h3 = __bfloat162float(__float2bfloat16(p3));
                ph[kg][half * 2 + 0] = pack_bf2(p0, p1);
                ph[kg][half * 2 + 1] = pack_bf2(p2, p3);
                pl[kg][half * 2 + 0] = pack_bf2(p0 - h0, p1 - h1);
                pl[kg][half * 2 + 1] = pack_bf2(p2 - h2, p3 - h3);
            }
        }
        l0r = l0r * al0 + sum0;
        l1r = l1r * al1 + sum1;
        #pragma unroll
        for (int nb = 0; nb < 8; nb++) {
            o[nb][0] *= al0; o[nb][1] *= al0;
            o[nb][2] *= al1; o[nb][3] *= al1;
        }
        #pragma unroll
        for (int kg = 0; kg < 4; kg++) {
            #pragma unroll
            for (int ep = 0; ep < 4; ep++) {
                uint32_t vo = aoff(kg * 16 + (lane & 15), ep * 2 + khalf);
                uint32_t vbh[4], vbl[4];
                LDM4T(vbh, Vh + vo);
                LDM4T(vbl, Vl + vo);
                #pragma unroll
                for (int half = 0; half < 2; half++) {
                    float* d = o[ep * 2 + half];
                    MMA16816(d, ph[kg], vbh[half * 2], vbh[half * 2 + 1]);
                    MMA16816(d, ph[kg], vbl[half * 2], vbl[half * 2 + 1]);
                    MMA16816(d, pl[kg], vbh[half * 2], vbh[half * 2 + 1]);
                }
            }
        }
    }
    l0r += __shfl_xor_sync(0xffffffffu, l0r, 1);
    l0r += __shfl_xor_sync(0xffffffffu, l0r, 2);
    l1r += __shfl_xor_sync(0xffffffffu, l1r, 1);
    l1r += __shfl_xor_sync(0xffffffffu, l1r, 2);
    float inv0 = 1.f / l0r, inv1 = 1.f / l1r;
    int r0 = q0 + wid * 16 + g, r1 = r0 + 8;
    #pragma unroll
    for (int eb = 0; eb < 8; eb++) {
        int col = h * 64 + eb * 8 + t * 2;
        size_t o0 = (size_t)(b * SS + r0) * DD + col;
        size_t o1 = (size_t)(b * SS + r1) * DD + col;
        float v00 = o[eb][0] * inv0, v01 = o[eb][1] * inv0;
        float v10 = o[eb][2] * inv1, v11 = o[eb][3] * inv1;
        __nv_bfloat16 h0, l0, h1, l1, h2, l2, h3, l3;
        split_bf16(v00, h0, l0); split_bf16(v01, h1, l1);
        split_bf16(v10, h2, l2); split_bf16(v11, h3, l3);
        *(__nv_bfloat162*)(ohi + o0) = __halves2bfloat162(h0, h1);
        *(__nv_bfloat162*)(olo + o0) = __halves2bfloat162(l0, l1);
        *(__nv_bfloat162*)(ohi + o1) = __halves2bfloat162(h2, h3);
        *(__nv_bfloat162*)(olo + o1) = __halves2bfloat162(l2, l3);
    }
}

// ================= launch =================
extern "C" void kernel_launch(void* const* d_in, const int* in_sizes, int n_in,
                              void* d_out, int out_size)
{
    const float* x   = (const float*)d_in[0];
    const float* Wq  = (const float*)d_in[1];
    const float* bq  = (const float*)d_in[2];
    const float* Wk  = (const float*)d_in[3];
    const float* bk  = (const float*)d_in[4];
    const float* Wv  = (const float*)d_in[5];
    const float* bv  = (const float*)d_in[6];
    const float* Wo  = (const float*)d_in[7];
    const float* bo  = (const float*)d_in[8];
    const float* W1  = (const float*)d_in[9];
    const float* b1  = (const float*)d_in[10];
    const float* W2  = (const float*)d_in[11];
    const float* b2  = (const float*)d_in[12];
    const float* g1  = (const float*)d_in[13];
    const float* be1 = (const float*)d_in[14];
    const float* g2  = (const float*)d_in[15];
    const float* be2 = (const float*)d_in[16];
    float* out = (float*)d_out;

    void *ppart, *pbp, *phh, *phl, *pqh, *pql, *poh, *pol, *pfh, *pfl;
    void *pWoh, *pWol, *pW1h, *pW1l, *pW2h, *pW2l, *pWqh, *pWql;
    cudaGetSymbolAddress(&ppart, g_part);
    cudaGetSymbolAddress(&pbp,  g_bp);
    cudaGetSymbolAddress(&phh,  g_h_hi);  cudaGetSymbolAddress(&phl, g_h_lo);
    cudaGetSymbolAddress(&pqh,  g_qkvh);  cudaGetSymbolAddress(&pql, g_qkvl);
    cudaGetSymbolAddress(&poh,  g_o_hi);  cudaGetSymbolAddress(&pol, g_o_lo);
    cudaGetSymbolAddress(&pfh,  g_f_hi);  cudaGetSymbolAddress(&pfl, g_f_lo);
    cudaGetSymbolAddress(&pWqh, g_Wqkv_hi); cudaGetSymbolAddress(&pWql, g_Wqkv_lo);
    cudaGetSymbolAddress(&pWoh, g_Wo_hi);   cudaGetSymbolAddress(&pWol, g_Wo_lo);
    cudaGetSymbolAddress(&pW1h, g_W1_hi);   cudaGetSymbolAddress(&pW1l, g_W1_lo);
    cudaGetSymbolAddress(&pW2h, g_W2_hi);   cudaGetSymbolAddress(&pW2l, g_W2_lo);
    float* part = (float*)ppart;
    float* bp   = (float*)pbp;
    __nv_bfloat16* hh = (__nv_bfloat16*)phh, *hl = (__nv_bfloat16*)phl;
    __nv_bfloat16* qvh = (__nv_bfloat16*)pqh, *qvl = (__nv_bfloat16*)pql;
    __nv_bfloat16* oh = (__nv_bfloat16*)poh, *ol = (__nv_bfloat16*)pol;
    __nv_bfloat16* fh = (__nv_bfloat16*)pfh, *fl = (__nv_bfloat16*)pfl;
    __nv_bfloat16* Wqh = (__nv_bfloat16*)pWqh, *Wql = (__nv_bfloat16*)pWql;
    __nv_bfloat16* Woh = (__nv_bfloat16*)pWoh, *Wol = (__nv_bfloat16*)pWol;
    __nv_bfloat16* W1h = (__nv_bfloat16*)pW1h, *W1l = (__nv_bfloat16*)pW1l;
    __nv_bfloat16* W2h = (__nv_bfloat16*)pW2h, *W2l = (__nv_bfloat16*)pW2l;

    cudaFuncSetAttribute(tgemm<0,1,0>, cudaFuncAttributeMaxDynamicSharedMemorySize, GEMM_SMEM);
    cudaFuncSetAttribute(tgemm<0,0,1>, cudaFuncAttributeMaxDynamicSharedMemorySize, GEMM_SMEM);
    cudaFuncSetAttribute(tgemm<1,1,0>, cudaFuncAttributeMaxDynamicSharedMemorySize, GEMM_SMEM);
    cudaFuncSetAttribute(attn_tc,      cudaFuncAttributeMaxDynamicSharedMemorySize, ATT_SMEM);

    // weight prep (coalesced transposes)
    qkv_cvt_t<<<dim3(DD/32, HDD/32, 3*HH), dim3(32,8)>>>(Wq, Wk, Wv);
    qkv_bias<<<(NC + 255)/256, 256>>>(bq, bk, bv);
    tcvt_t<<<dim3(DD/32, DD/32),  dim3(32,8)>>>(Wo, Woh, Wol, DD, DD);
    tcvt_t<<<dim3(FF/32, DD/32),  dim3(32,8)>>>(W1, W1h, W1l, DD, FF);
    tcvt_t<<<dim3(DD/32, FF/32),  dim3(32,8)>>>(W2, W2h, W2l, FF, DD);
    // LN1 -> split
    ln_kernel<<<ROWS, 256>>>(x, g1, be1, hh, hl);
    // QKV projection -> split bf16 qkv
    tgemm<0,1,0><<<dim3(NC/128, ROWS/128), 128, GEMM_SMEM>>>(
        hh, hl, Wqh, Wql, bp, nullptr, qvh, qvl, NC, DD);
    // tensor-core flash attention (64-row Q tile, 2 CTAs/SM) -> split bf16 o
    attn_tc<<<dim3(SS/64, BB*HH), 128, ATT_SMEM>>>(qvh, qvl, oh, ol);
    // output projection: split-K=3 partials
    tgemm<0,0,1><<<dim3(DD/128, ROWS/128, 3), 128, GEMM_SMEM>>>(
        oh, ol, Woh, Wol, nullptr, part, nullptr, nullptr, DD, DD);
    // fused reduce + bias + LN2 -> split
    ln2_fuse<<<ROWS, 256>>>(bo, g2, be2, hh, hl);
    // FFN up + GELU -> split
    tgemm<1,1,0><<<dim3(FF/128, ROWS/128), 128, GEMM_SMEM>>>(
        hh, hl, W1h, W1l, b1, nullptr, fh, fl, FF, DD);
    // FFN down: split-K=3 partials
    tgemm<0,0,1><<<dim3(DD/128, ROWS/128, 3), 128, GEMM_SMEM>>>(
        fh, fl, W2h, W2l, nullptr, part, nullptr, nullptr, DD, FF);
    // reduce + bias -> output
    addbias3<<<(ROWS*DD/4 + 255)/256, 256>>>(b2, out);
}

// round 15
// speedup vs baseline: 1.0170x; 1.0170x over previous
#include <cuda_runtime.h>
#include <cuda_bf16.h>
#include <math.h>
#include <stdint.h>

// Problem constants
#define BB   4
#define SS   2048
#define DD   768
#define HH   12
#define HDD  64
#define FF   3072
#define ROWS (BB*SS)   // 8192
#define NC   2304      // 3*DD packed qkv cols

// ---------------- scratch (device globals; no runtime allocation) ----------
__device__ float g_part[3*(size_t)ROWS*DD];      // split-K fp32 partials (3 planes)
__device__ float g_bp [NC];                      // packed QKV bias
__device__ __align__(256) __nv_bfloat16 g_h_hi[ROWS*DD], g_h_lo[ROWS*DD];
__device__ __align__(256) __nv_bfloat16 g_qkvh[ROWS*NC], g_qkvl[ROWS*NC];   // split qkv
__device__ __align__(256) __nv_bfloat16 g_o_hi[ROWS*DD], g_o_lo[ROWS*DD];
__device__ __align__(256) __nv_bfloat16 g_f_hi[ROWS*FF], g_f_lo[ROWS*FF];
__device__ __align__(256) __nv_bfloat16 g_Wqkv_hi[NC*DD], g_Wqkv_lo[NC*DD]; // [2304][768]
__device__ __align__(256) __nv_bfloat16 g_Wo_hi[DD*DD],  g_Wo_lo[DD*DD];    // [768][768]
__device__ __align__(256) __nv_bfloat16 g_W1_hi[FF*DD],  g_W1_lo[FF*DD];    // [3072][768]
__device__ __align__(256) __nv_bfloat16 g_W2_hi[DD*FF],  g_W2_lo[DD*FF];    // [768][3072]

// ================= PTX helpers (baseline ISA only: sm_80-class) =============
__device__ __forceinline__ uint32_t smem_u32(const void* p) {
    uint32_t a;
    asm("{ .reg .u64 t; cvta.to.shared.u64 t, %1; cvt.u32.u64 %0, t; }" : "=r"(a) : "l"(p));
    return a;
}
#define CP16(dst, src) asm volatile("cp.async.cg.shared.global [%0], [%1], 16;" :: "r"(dst), "l"(src))
#define CP_COMMIT()    asm volatile("cp.async.commit_group;" ::: "memory")
#define CP_WAIT(n)     asm volatile("cp.async.wait_group %0;" :: "n"(n) : "memory")

#define LDM4(r, addr) \
    asm volatile("ldmatrix.sync.aligned.m8n8.x4.shared.b16 {%0,%1,%2,%3}, [%4];" \
        : "=r"((r)[0]), "=r"((r)[1]), "=r"((r)[2]), "=r"((r)[3]) : "r"(addr))
#define LDM4T(r, addr) \
    asm volatile("ldmatrix.sync.aligned.m8n8.x4.trans.shared.b16 {%0,%1,%2,%3}, [%4];" \
        : "=r"((r)[0]), "=r"((r)[1]), "=r"((r)[2]), "=r"((r)[3]) : "r"(addr))

#define MMA16816(d, a, b0v, b1v) \
    asm volatile("mma.sync.aligned.m16n8k16.row.col.f32.bf16.bf16.f32 " \
        "{%0,%1,%2,%3},{%4,%5,%6,%7},{%8,%9},{%0,%1,%2,%3};" \
        : "+f"((d)[0]), "+f"((d)[1]), "+f"((d)[2]), "+f"((d)[3]) \
        : "r"((a)[0]), "r"((a)[1]), "r"((a)[2]), "r"((a)[3]), "r"(b0v), "r"(b1v))

__device__ __forceinline__ void split_bf16(float v, __nv_bfloat16& hi, __nv_bfloat16& lo) {
    hi = __float2bfloat16(v);
    lo = __float2bfloat16(v - __bfloat162float(hi));
}
__device__ __forceinline__ uint32_t pack_bf2(float a, float b) {
    __nv_bfloat162 t = __halves2bfloat162(__float2bfloat16(a), __float2bfloat16(b));
    return *(uint32_t*)&t;
}
__device__ __forceinline__ float gelu_exact(float x) {
    return 0.5f * x * (1.0f + erff(x * 0.70710678118654752f));
}

// ================= weight conversion (coalesced transposes) =================
// W[K][N] fp32 -> O[N][K] split bf16, 32x32 smem tiles.
__global__ void tcvt_t(const float* __restrict__ W, __nv_bfloat16* __restrict__ Ohi,
                       __nv_bfloat16* __restrict__ Olo, int K, int N)
{
    __shared__ float t[32][33];
    int n0 = blockIdx.x * 32, k0 = blockIdx.y * 32;
    int tx = threadIdx.x, ty = threadIdx.y;
    #pragma unroll
    for (int j = 0; j < 4; j++)
        t[ty + 8 * j][tx] = W[(size_t)(k0 + ty + 8 * j) * N + n0 + tx];
    __syncthreads();
    #pragma unroll
    for (int j = 0; j < 4; j++) {
        int n = n0 + ty + 8 * j;
        float v = t[tx][ty + 8 * j];
        __nv_bfloat16 hi, lo; split_bf16(v, hi, lo);
        Ohi[(size_t)n * K + k0 + tx] = hi;
        Olo[(size_t)n * K + k0 + tx] = lo;
    }
}
// Wq/Wk/Wv [H][D][HD] -> g_Wqkv[(part*768+h*64+e)][d], transposed per (part,h)
__global__ void qkv_cvt_t(const float* __restrict__ Wq, const float* __restrict__ Wk,
                          const float* __restrict__ Wv)
{
    __shared__ float t[32][33];
    int d0 = blockIdx.x * 32, e0 = blockIdx.y * 32;
    int part = blockIdx.z / HH, h = blockIdx.z % HH;
    const float* W = (part == 0) ? Wq : (part == 1) ? Wk : Wv;
    int tx = threadIdx.x, ty = threadIdx.y;
    #pragma unroll
    for (int j = 0; j < 4; j++)
        t[ty + 8 * j][tx] = W[(size_t)(h * DD + d0 + ty + 8 * j) * HDD + e0 + tx];
    __syncthreads();
    #pragma unroll
    for (int j = 0; j < 4; j++) {
        int e = e0 + ty + 8 * j;
        int row = part * DD + h * HDD + e;
        float v = t[tx][ty + 8 * j];
        __nv_bfloat16 hi, lo; split_bf16(v, hi, lo);
        g_Wqkv_hi[(size_t)row * DD + d0 + tx] = hi;
        g_Wqkv_lo[(size_t)row * DD + d0 + tx] = lo;
    }
}
__global__ void qkv_bias(const float* __restrict__ bq, const float* __restrict__ bk,
                         const float* __restrict__ bv)
{
    int j = blockIdx.x * 256 + threadIdx.x;
    if (j >= NC) return;
    int part = j / DD, jj = j - part * DD;
    const float* bb = (part == 0) ? bq : (part == 1) ? bk : bv;
    g_bp[j] = bb[jj];
}

// ================= layer norm (writes split bf16) =================
__global__ void ln_kernel(const float* __restrict__ x, const float* __restrict__ g,
                          const float* __restrict__ b, __nv_bfloat16* __restrict__ yhi,
                          __nv_bfloat16* __restrict__ ylo)
{
    int row = blockIdx.x;
    int tid = threadIdx.x;
    const float* xr = x + (size_t)row * DD;
    float v0 = xr[tid], v1 = xr[tid + 256], v2 = xr[tid + 512];
    float s  = v0 + v1 + v2;
    float ss = v0 * v0 + v1 * v1 + v2 * v2;
    #pragma unroll
    for (int o = 16; o >= 1; o >>= 1) {
        s  += __shfl_xor_sync(0xffffffffu, s,  o);
        ss += __shfl_xor_sync(0xffffffffu, ss, o);
    }
    __shared__ float rs[8], rss[8];
    int w = tid >> 5, l = tid & 31;
    if (l == 0) { rs[w] = s; rss[w] = ss; }
    __syncthreads();
    float S = 0.f, S2 = 0.f;
    #pragma unroll
    for (int i = 0; i < 8; i++) { S += rs[i]; S2 += rss[i]; }
    float mu  = S  * (1.0f / DD);
    float var = S2 * (1.0f / DD) - mu * mu;
    float inv = rsqrtf(var + 1e-5f);
    #pragma unroll
    for (int q = 0; q < 3; q++) {
        int c = tid + q * 256;
        float v = (q == 0 ? v0 : q == 1 ? v1 : v2);
        float y = (v - mu) * inv * g[c] + b[c];
        __nv_bfloat16 hi, lo; split_bf16(y, hi, lo);
        yhi[(size_t)row * DD + c] = hi;
        ylo[(size_t)row * DD + c] = lo;
    }
}

// LN2 fused over 3 split-K partials + bias (a = sum + bo; y = LN(a) -> split)
__global__ void ln2_fuse(const float* __restrict__ bo, const float* __restrict__ g,
                         const float* __restrict__ b, __nv_bfloat16* __restrict__ yhi,
                         __nv_bfloat16* __restrict__ ylo)
{
    const size_t plane = (size_t)ROWS * DD;
    int row = blockIdx.x;
    int tid = threadIdx.x;
    const float* p = g_part + (size_t)row * DD;
    float v[3];
    #pragma unroll
    for (int q = 0; q < 3; q++) {
        int c = tid + q * 256;
        v[q] = p[c] + p[plane + c] + p[2 * plane + c] + bo[c];
    }
    float s  = v[0] + v[1] + v[2];
    float ss = v[0]*v[0] + v[1]*v[1] + v[2]*v[2];
    #pragma unroll
    for (int o = 16; o >= 1; o >>= 1) {
        s  += __shfl_xor_sync(0xffffffffu, s,  o);
        ss += __shfl_xor_sync(0xffffffffu, ss, o);
    }
    __shared__ float rs[8], rss[8];
    int w = tid >> 5, l = tid & 31;
    if (l == 0) { rs[w] = s; rss[w] = ss; }
    __syncthreads();
    float S = 0.f, S2 = 0.f;
    #pragma unroll
    for (int i = 0; i < 8; i++) { S += rs[i]; S2 += rss[i]; }
    float mu  = S  * (1.0f / DD);
    float var = S2 * (1.0f / DD) - mu * mu;
    float inv = rsqrtf(var + 1e-5f);
    #pragma unroll
    for (int q = 0; q < 3; q++) {
        int c = tid + q * 256;
        float y = (v[q] - mu) * inv * g[c] + b[c];
        __nv_bfloat16 hi, lo; split_bf16(y, hi, lo);
        yhi[(size_t)row * DD + c] = hi;
        ylo[(size_t)row * DD + c] = lo;
    }
}

// out = p0 + p1 + p2 + bias (FFN2 reduce)
__global__ void addbias3(const float* __restrict__ bias, float* __restrict__ out)
{
    const size_t plane = (size_t)ROWS * DD;
    size_t i4 = ((size_t)blockIdx.x * 256 + threadIdx.x) * 4;
    if (i4 >= plane) return;
    int c = (int)(i4 % DD);
    float4 a = *(const float4*)(g_part + i4);
    float4 b = *(const float4*)(g_part + plane + i4);
    float4 d = *(const float4*)(g_part + 2 * plane + i4);
    float4 bb = *(const float4*)(bias + c);
    float4 r;
    r.x = a.x + b.x + d.x + bb.x;
    r.y = a.y + b.y + d.y + bb.y;
    r.z = a.z + b.z + d.z + bb.z;
    r.w = a.w + b.w + d.w + bb.w;
    *(float4*)(out + i4) = r;
}

// ================ mma.sync GEMM: C[M,N] = A[M,K] @ Bt[N,K]^T ================
// R12-validated config: 8 warps (4x2), 32x64 warp tile, 256 threads, 2 CTAs/SM,
// single-barrier 3-stage pipeline with loads issued before compute.
#define STAGE_B  32768
#define GEMM_SMEM (3*STAGE_B)

template<int ACT, int OSPLIT, int PART>
__global__ __launch_bounds__(256, 2)
void tgemm(const __nv_bfloat16* __restrict__ Ahi, const __nv_bfloat16* __restrict__ Alo,
           const __nv_bfloat16* __restrict__ Bhi, const __nv_bfloat16* __restrict__ Blo,
           const float* __restrict__ bias,
           float* __restrict__ Cf, __nv_bfloat16* __restrict__ Chi,
           __nv_bfloat16* __restrict__ Clo, int N, int K)
{
    extern __shared__ char smem[];
    uint32_t ST = smem_u32(smem);
    int tid = threadIdx.x;
    int lane = tid & 31, wid = tid >> 5;
    int wr = wid & 3, wc = wid >> 2;          // warp grid 4 x 2
    int m0 = blockIdx.y * 128;
    int n0 = blockIdx.x * 128;
    int KH = PART ? (K / (int)gridDim.z) : K;
    int koff = PART ? ((int)blockIdx.z * KH) : 0;
    int nc = KH >> 5;                          // K chunks of 32

    const __nv_bfloat16* Abase_h = Ahi + (size_t)m0 * K + koff;
    const __nv_bfloat16* Abase_l = Alo + (size_t)m0 * K + koff;
    const __nv_bfloat16* Bbase_h = Bhi + (size_t)n0 * K + koff;
    const __nv_bfloat16* Bbase_l = Blo + (size_t)n0 * K + koff;

    auto load_chunk = [&](int c, int p) {
        uint32_t base = ST + p * STAGE_B;
        const __nv_bfloat16* ah = Abase_h + c * 32;
        const __nv_bfloat16* al = Abase_l + c * 32;
        const __nv_bfloat16* bh = Bbase_h + c * 32;
        const __nv_bfloat16* bl = Bbase_l + c * 32;
        #pragma unroll
        for (int j = 0; j < 2; j++) {
            int id = tid + 256 * j;            // 0..511 : 128 rows x 4 chunks
            int r = id >> 2, cc = id & 3;
            uint32_t off = (uint32_t)(r * 64 + ((cc ^ ((r >> 1) & 3)) << 4));
            const size_t go = (size_t)r * K + cc * 8;
            CP16(base +         off, ah + go);
            CP16(base +  8192 + off, al + go);
            CP16(base + 16384 + off, bh + go);
            CP16(base + 24576 + off, bl + go);
        }
    };

    float acc[2][8][4];
    #pragma unroll
    for (int s = 0; s < 2; s++)
        #pragma unroll
        for (int t = 0; t < 8; t++)
            #pragma unroll
            for (int q = 0; q < 4; q++) acc[s][t][q] = 0.f;

    load_chunk(0, 0); CP_COMMIT();
    load_chunk(1, 1); CP_COMMIT();

    int arow = wr * 32 + (lane & 15);
    int brow = wc * 64 + (lane & 15);
    int khalf = lane >> 4;

    for (int c = 0; c < nc; c++) {
        CP_WAIT(1);                 // chunk c landed (next group may be in flight)
        __syncthreads();            // all warps past iter c-1 (stage (c+2)%3 free)
        if (c + 2 < nc) load_chunk(c + 2, (c + 2) % 3);
        CP_COMMIT();                // empty when skipped: uniform group count
        uint32_t base = ST + (c % 3) * STAGE_B;
        uint32_t Ah = base, Al = base + 8192, Bh = base + 16384, Bl = base + 24576;
        #pragma unroll
        for (int ks = 0; ks < 2; ks++) {
            uint32_t ahf[2][4], alf[2][4];
            #pragma unroll
            for (int sub = 0; sub < 2; sub++) {
                int r = arow + sub * 16;
                int kc = ks * 2 + khalf;
                uint32_t off = (uint32_t)(r * 64 + ((kc ^ ((r >> 1) & 3)) << 4));
                LDM4(ahf[sub], Ah + off);
                LDM4(alf[sub], Al + off);
            }
            #pragma unroll
            for (int nh = 0; nh < 4; nh++) {
                int n = brow + nh * 16;
                int kc = ks * 2 + khalf;
                uint32_t off = (uint32_t)(n * 64 + ((kc ^ ((n >> 1) & 3)) << 4));
                uint32_t bhf[4], blf[4];
                LDM4(bhf, Bh + off);
                LDM4(blf, Bl + off);
                #pragma unroll
                for (int sub = 0; sub < 2; sub++) {
                    #pragma unroll
                    for (int nt = 0; nt < 2; nt++) {
                        float* d = acc[sub][nh * 2 + nt];
                        MMA16816(d, ahf[sub], bhf[nt], bhf[nt + 2]);
                        MMA16816(d, ahf[sub], blf[nt], blf[nt + 2]);
                        MMA16816(d, alf[sub], bhf[nt], bhf[nt + 2]);
                    }
                }
            }
        }
    }

    // ---------------- epilogue ----------------
    float* Cpart = PART ? (Cf + (size_t)blockIdx.z * ROWS * N) : Cf;
    int g = lane >> 2, t = lane & 3;
    #pragma unroll
    for (int sub = 0; sub < 2; sub++) {
        #pragma unroll
        for (int nt8 = 0; nt8 < 8; nt8++) {
            int col = n0 + wc * 64 + nt8 * 8 + t * 2;
            float b0 = PART ? 0.f : bias[col];
            float b1 = PART ? 0.f : bias[col + 1];
            #pragma unroll
            for (int half = 0; half < 2; half++) {
                int row = m0 + wr * 32 + sub * 16 + g + half * 8;
                float v0 = acc[sub][nt8][half * 2 + 0] + b0;
                float v1 = acc[sub][nt8][half * 2 + 1] + b1;
                if (ACT) { v0 = gelu_exact(v0); v1 = gelu_exact(v1); }
                if (OSPLIT) {
                    __nv_bfloat16 h0, l0, h1, l1;
                    split_bf16(v0, h0, l0); split_bf16(v1, h1, l1);
                    *(__nv_bfloat162*)(Chi + (size_t)row * N + col) = __halves2bfloat162(h0, h1);
                    *(__nv_bfloat162*)(Clo + (size_t)row * N + col) = __halves2bfloat162(l0, l1);
                } else {
                    float2 fv; fv.x = v0; fv.y = v1;
                    *(float2*)(Cpart + (size_t)row * N + col) = fv;
                }
            }
        }
    }
}

// ============ tensor-core flash attention (bf16 split, 64x64 tiles) =========
// R12-validated config + Q-fragment hoist: Q ldmatrix operands are
// loop-invariant (Q smem written once, never overwritten), so they are loaded
// to registers ONCE before the kt loop (saves 8 of 72 LDM4 per iteration,
// ~11% of attention smem-crossbar traffic). Regs ~190/thread keeps 2 CTAs/SM.
#define ATT_STAGE 32768
#define ATT_SMEM  (16384 + 3*ATT_STAGE)

__device__ __forceinline__ uint32_t aoff(int r, int c) {
    return (uint32_t)((r << 7) + (((c ^ (r & 7)) & 7) << 4));
}

__global__ __launch_bounds__(128, 2)
void attn_tc(const __nv_bfloat16* __restrict__ qh, const __nv_bfloat16* __restrict__ ql,
             __nv_bfloat16* __restrict__ ohi, __nv_bfloat16* __restrict__ olo)
{
    extern __shared__ char sm[];
    uint32_t S0 = smem_u32(sm);
    const uint32_t Qh = S0, Ql = S0 + 8192;
    int tid = threadIdx.x, lane = tid & 31, wid = tid >> 5;
    int bh = blockIdx.y, b = bh / HH, h = bh - b * HH;
    int q0 = blockIdx.x * 64;
    size_t rowbase = (size_t)b * SS * NC + h * 64;
    const int NT = SS / 64;

    {
        const __nv_bfloat16* qph = qh + rowbase + (size_t)q0 * NC;
        const __nv_bfloat16* qpl = ql + rowbase + (size_t)q0 * NC;
        #pragma unroll
        for (int j = 0; j < 4; j++) {
            int id = tid + 128 * j; int r = id >> 3, c = id & 7;
            size_t go = (size_t)r * NC + c * 8;
            CP16(Qh + aoff(r, c), qph + go);
            CP16(Ql + aoff(r, c), qpl + go);
        }
        CP_COMMIT();
    }
    auto load_kv = [&](int kt, int p) {
        uint32_t base = S0 + 16384 + p * ATT_STAGE;
        size_t kb = rowbase + (size_t)(kt * 64) * NC + 768;
        size_t vb = kb + 768;
        #pragma unroll
        for (int j = 0; j < 4; j++) {
            int id = tid + 128 * j; int r = id >> 3, c = id & 7;
            uint32_t o_ = aoff(r, c);
            size_t go = (size_t)r * NC + c * 8;
            CP16(base +         o_, qh + kb + go);
            CP16(base +  8192 + o_, ql + kb + go);
            CP16(base + 16384 + o_, qh + vb + go);
            CP16(base + 24576 + o_, ql + vb + go);
        }
    };
    load_kv(0, 0); CP_COMMIT();
    load_kv(1, 1); CP_COMMIT();

    float o[8][4];
    #pragma unroll
    for (int i = 0; i < 8; i++)
        #pragma unroll
        for (int q = 0; q < 4; q++) o[i][q] = 0.f;
    float m0r = -1e30f, m1r = -1e30f, l0r = 0.f, l1r = 0.f;
    int g = lane >> 2, t = lane & 3;
    int arow = wid * 16 + (lane & 15);
    int khalf = lane >> 4;

    // ---- hoist Q fragments (loop-invariant) ----
    uint32_t qfh[4][4], qfl[4][4];
    {
        CP_WAIT(2);                 // Q group done (kv0/kv1 may be in flight)
        __syncthreads();            // Q smem visible across warps
        #pragma unroll
        for (int ks = 0; ks < 4; ks++) {
            uint32_t ao = aoff(arow, ks * 2 + khalf);
            LDM4(qfh[ks], Qh + ao);
            LDM4(qfl[ks], Ql + ao);
        }
    }

    for (int kt = 0; kt < NT; kt++) {
        int p = kt % 3;
        CP_WAIT(1);                 // stage kt landed (1 newer group in flight)
        __syncthreads();            // all warps past iter kt-1 (stage (kt+2)%3 free)
        if (kt + 2 < NT) load_kv(kt + 2, (kt + 2) % 3);
        CP_COMMIT();                // empty when skipped: uniform group count
        uint32_t base = S0 + 16384 + p * ATT_STAGE;
        uint32_t Kh = base, Kl = base + 8192, Vh = base + 16384, Vl = base + 24576;

        float s[8][4];
        #pragma unroll
        for (int i = 0; i < 8; i++)
            #pragma unroll
            for (int q = 0; q < 4; q++) s[i][q] = 0.f;
        #pragma unroll
        for (int ks = 0; ks < 4; ks++) {
            #pragma unroll
            for (int np = 0; np < 4; np++) {
                uint32_t bo = aoff(np * 16 + (lane & 15), ks * 2 + khalf);
                uint32_t kbh[4], kbl[4];
                LDM4(kbh, Kh + bo);
                LDM4(kbl, Kl + bo);
                #pragma unroll
                for (int half = 0; half < 2; half++) {
                    float* d = s[np * 2 + half];
                    MMA16816(d, qfh[ks], kbh[half], kbh[half + 2]);
                    MMA16816(d, qfh[ks], kbl[half], kbl[half + 2]);
                    MMA16816(d, qfl[ks], kbh[half], kbh[half + 2]);
                }
            }
        }
        float mn0 = m0r, mn1 = m1r;
        #pragma unroll
        for (int nb = 0; nb < 8; nb++) {
            s[nb][0] *= 0.125f; s[nb][1] *= 0.125f;
            s[nb][2] *= 0.125f; s[nb][3] *= 0.125f;
            mn0 = fmaxf(mn0, fmaxf(s[nb][0], s[nb][1]));
            mn1 = fmaxf(mn1, fmaxf(s[nb][2], s[nb][3]));
        }
        mn0 = fmaxf(mn0, __shfl_xor_sync(0xffffffffu, mn0, 1));
        mn0 = fmaxf(mn0, __shfl_xor_sync(0xffffffffu, mn0, 2));
        mn1 = fmaxf(mn1, __shfl_xor_sync(0xffffffffu, mn1, 1));
        mn1 = fmaxf(mn1, __shfl_xor_sync(0xffffffffu, mn1, 2));
        float al0 = __expf(m0r - mn0), al1 = __expf(m1r - mn1);
        m0r = mn0; m1r = mn1;
        float sum0 = 0.f, sum1 = 0.f;
        uint32_t ph[4][4], pl[4][4];
        #pragma unroll
        for (int kg = 0; kg < 4; kg++) {
            #pragma unroll
            for (int half = 0; half < 2; half++) {
                int nb = kg * 2 + half;
                float p0 = __expf(s[nb][0] - mn0), p1 = __expf(s[nb][1] - mn0);
                float p2 = __expf(s[nb][2] - mn1), p3 = __expf(s[nb][3] - mn1);
                sum0 += p0 + p1; sum1 += p2 + p3;
                float h0 = __bfloat162float(__float2bfloat16(p0));
                float h1 = __bfloat162float(__float2bfloat16(p1));
                float h2 = __bfloat162float(__float2bfloat16(p2));
                float h3 = __bfloat162float(__float2bfloat16(p3));
                ph[kg][half * 2 + 0] = pack_bf2(p0, p1);
                ph[kg][half * 2 + 1] = pack_bf2(p2, p3);
                pl[kg][half * 2 + 0] = pack_bf2(p0 - h0, p1 - h1);
                pl[kg][half * 2 + 1] = pack_bf2(p2 - h2, p3 - h3);
            }
        }
        l0r = l0r * al0 + sum0;
        l1r = l1r * al1 + sum1;
        #pragma unroll
        for (int nb = 0; nb < 8; nb++) {
            o[nb][0] *= al0; o[nb][1] *= al0;
            o[nb][2] *= al1; o[nb][3] *= al1;
        }
        #pragma unroll
        for (int kg = 0; kg < 4; kg++) {
            #pragma unroll
            for (int ep = 0; ep < 4; ep++) {
                uint32_t vo = aoff(kg * 16 + (lane & 15), ep * 2 + khalf);
                uint32_t vbh[4], vbl[4];
                LDM4T(vbh, Vh + vo);
                LDM4T(vbl, Vl + vo);
                #pragma unroll
                for (int half = 0; half < 2; half++) {
                    float* d = o[ep * 2 + half];
                    MMA16816(d, ph[kg], vbh[half * 2], vbh[half * 2 + 1]);
                    MMA16816(d, ph[kg], vbl[half * 2], vbl[half * 2 + 1]);
                    MMA16816(d, pl[kg], vbh[half * 2], vbh[half * 2 + 1]);
                }
            }
        }
    }
    l0r += __shfl_xor_sync(0xffffffffu, l0r, 1);
    l0r += __shfl_xor_sync(0xffffffffu, l0r, 2);
    l1r += __shfl_xor_sync(0xffffffffu, l1r, 1);
    l1r += __shfl_xor_sync(0xffffffffu, l1r, 2);
    float inv0 = 1.f / l0r, inv1 = 1.f / l1r;
    int r0 = q0 + wid * 16 + g, r1 = r0 + 8;
    #pragma unroll
    for (int eb = 0; eb < 8; eb++) {
        int col = h * 64 + eb * 8 + t * 2;
        size_t o0 = (size_t)(b * SS + r0) * DD + col;
        size_t o1 = (size_t)(b * SS + r1) * DD + col;
        float v00 = o[eb][0] * inv0, v01 = o[eb][1] * inv0;
        float v10 = o[eb][2] * inv1, v11 = o[eb][3] * inv1;
        __nv_bfloat16 h0, l0, h1, l1, h2, l2, h3, l3;
        split_bf16(v00, h0, l0); split_bf16(v01, h1, l1);
        split_bf16(v10, h2, l2); split_bf16(v11, h3, l3);
        *(__nv_bfloat162*)(ohi + o0) = __halves2bfloat162(h0, h1);
        *(__nv_bfloat162*)(olo + o0) = __halves2bfloat162(l0, l1);
        *(__nv_bfloat162*)(ohi + o1) = __halves2bfloat162(h2, h3);
        *(__nv_bfloat162*)(olo + o1) = __halves2bfloat162(l2, l3);
    }
}

// ================= launch =================
extern "C" void kernel_launch(void* const* d_in, const int* in_sizes, int n_in,
                              void* d_out, int out_size)
{
    const float* x   = (const float*)d_in[0];
    const float* Wq  = (const float*)d_in[1];
    const float* bq  = (const float*)d_in[2];
    const float* Wk  = (const float*)d_in[3];
    const float* bk  = (const float*)d_in[4];
    const float* Wv  = (const float*)d_in[5];
    const float* bv  = (const float*)d_in[6];
    const float* Wo  = (const float*)d_in[7];
    const float* bo  = (const float*)d_in[8];
    const float* W1  = (const float*)d_in[9];
    const float* b1  = (const float*)d_in[10];
    const float* W2  = (const float*)d_in[11];
    const float* b2  = (const float*)d_in[12];
    const float* g1  = (const float*)d_in[13];
    const float* be1 = (const float*)d_in[14];
    const float* g2  = (const float*)d_in[15];
    const float* be2 = (const float*)d_in[16];
    float* out = (float*)d_out;

    void *ppart, *pbp, *phh, *phl, *pqh, *pql, *poh, *pol, *pfh, *pfl;
    void *pWoh, *pWol, *pW1h, *pW1l, *pW2h, *pW2l, *pWqh, *pWql;
    cudaGetSymbolAddress(&ppart, g_part);
    cudaGetSymbolAddress(&pbp,  g_bp);
    cudaGetSymbolAddress(&phh,  g_h_hi);  cudaGetSymbolAddress(&phl, g_h_lo);
    cudaGetSymbolAddress(&pqh,  g_qkvh);  cudaGetSymbolAddress(&pql, g_qkvl);
    cudaGetSymbolAddress(&poh,  g_o_hi);  cudaGetSymbolAddress(&pol, g_o_lo);
    cudaGetSymbolAddress(&pfh,  g_f_hi);  cudaGetSymbolAddress(&pfl, g_f_lo);
    cudaGetSymbolAddress(&pWqh, g_Wqkv_hi); cudaGetSymbolAddress(&pWql, g_Wqkv_lo);
    cudaGetSymbolAddress(&pWoh, g_Wo_hi);   cudaGetSymbolAddress(&pWol, g_Wo_lo);
    cudaGetSymbolAddress(&pW1h, g_W1_hi);   cudaGetSymbolAddress(&pW1l, g_W1_lo);
    cudaGetSymbolAddress(&pW2h, g_W2_hi);   cudaGetSymbolAddress(&pW2l, g_W2_lo);
    float* part = (float*)ppart;
    float* bp   = (float*)pbp;
    __nv_bfloat16* hh = (__nv_bfloat16*)phh, *hl = (__nv_bfloat16*)phl;
    __nv_bfloat16* qvh = (__nv_bfloat16*)pqh, *qvl = (__nv_bfloat16*)pql;
    __nv_bfloat16* oh = (__nv_bfloat16*)poh, *ol = (__nv_bfloat16*)pol;
    __nv_bfloat16* fh = (__nv_bfloat16*)pfh, *fl = (__nv_bfloat16*)pfl;
    __nv_bfloat16* Wqh = (__nv_bfloat16*)pWqh, *Wql = (__nv_bfloat16*)pWql;
    __nv_bfloat16* Woh = (__nv_bfloat16*)pWoh, *Wol = (__nv_bfloat16*)pWol;
    __nv_bfloat16* W1h = (__nv_bfloat16*)pW1h, *W1l = (__nv_bfloat16*)pW1l;
    __nv_bfloat16* W2h = (__nv_bfloat16*)pW2h, *W2l = (__nv_bfloat16*)pW2l;

    cudaFuncSetAttribute(tgemm<0,1,0>, cudaFuncAttributeMaxDynamicSharedMemorySize, GEMM_SMEM);
    cudaFuncSetAttribute(tgemm<0,0,1>, cudaFuncAttributeMaxDynamicSharedMemorySize, GEMM_SMEM);
    cudaFuncSetAttribute(tgemm<1,1,0>, cudaFuncAttributeMaxDynamicSharedMemorySize, GEMM_SMEM);
    cudaFuncSetAttribute(attn_tc,      cudaFuncAttributeMaxDynamicSharedMemorySize, ATT_SMEM);

    // weight prep (coalesced transposes)
    qkv_cvt_t<<<dim3(DD/32, HDD/32, 3*HH), dim3(32,8)>>>(Wq, Wk, Wv);
    qkv_bias<<<(NC + 255)/256, 256>>>(bq, bk, bv);
    tcvt_t<<<dim3(DD/32, DD/32),  dim3(32,8)>>>(Wo, Woh, Wol, DD, DD);
    tcvt_t<<<dim3(FF/32, DD/32),  dim3(32,8)>>>(W1, W1h, W1l, DD, FF);
    tcvt_t<<<dim3(DD/32, FF/32),  dim3(32,8)>>>(W2, W2h, W2l, FF, DD);
    // LN1 -> split
    ln_kernel<<<ROWS, 256>>>(x, g1, be1, hh, hl);
    // QKV projection -> split bf16 qkv
    tgemm<0,1,0><<<dim3(NC/128, ROWS/128), 256, GEMM_SMEM>>>(
        hh, hl, Wqh, Wql, bp, nullptr, qvh, qvl, NC, DD);
    // tensor-core flash attention (64-row Q tile, 2 CTAs/SM) -> split bf16 o
    attn_tc<<<dim3(SS/64, BB*HH), 128, ATT_SMEM>>>(qvh, qvl, oh, ol);
    // output projection: split-K=3 partials
    tgemm<0,0,1><<<dim3(DD/128, ROWS/128, 3), 256, GEMM_SMEM>>>(
        oh, ol, Woh, Wol, nullptr, part, nullptr, nullptr, DD, DD);
    // fused reduce + bias + LN2 -> split
    ln2_fuse<<<ROWS, 256>>>(bo, g2, be2, hh, hl);
    // FFN up + GELU -> split
    tgemm<1,1,0><<<dim3(FF/128, ROWS/128), 256, GEMM_SMEM>>>(
        hh, hl, W1h, W1l, b1, nullptr, fh, fl, FF, DD);
    // FFN down: split-K=3 partials
    tgemm<0,0,1><<<dim3(DD/128, ROWS/128, 3), 256, GEMM_SMEM>>>(
        fh, fl, W2h, W2l, nullptr, part, nullptr, nullptr, DD, FF);
    // reduce + bias -> output
    addbias3<<<(ROWS*DD/4 + 255)/256, 256>>>(b2, out);
}

// round 16
// speedup vs baseline: 1.0248x; 1.0077x over previous
#include <cuda_runtime.h>
#include <cuda_bf16.h>
#include <math.h>
#include <stdint.h>

// Problem constants
#define BB   4
#define SS   2048
#define DD   768
#define HH   12
#define HDD  64
#define FF   3072
#define ROWS (BB*SS)   // 8192
#define NC   2304      // 3*DD packed qkv cols

// ---------------- scratch (device globals; no runtime allocation) ----------
__device__ float g_part[3*(size_t)ROWS*DD];      // split-K fp32 partials (3 planes)
__device__ float g_bp [NC];                      // packed QKV bias
__device__ __align__(256) __nv_bfloat16 g_h_hi[ROWS*DD], g_h_lo[ROWS*DD];
__device__ __align__(256) __nv_bfloat16 g_qkvh[ROWS*NC], g_qkvl[ROWS*NC];   // split qkv
__device__ __align__(256) __nv_bfloat16 g_o_hi[ROWS*DD], g_o_lo[ROWS*DD];
__device__ __align__(256) __nv_bfloat16 g_f_hi[ROWS*FF], g_f_lo[ROWS*FF];
__device__ __align__(256) __nv_bfloat16 g_Wqkv_hi[NC*DD], g_Wqkv_lo[NC*DD]; // [2304][768]
__device__ __align__(256) __nv_bfloat16 g_Wo_hi[DD*DD],  g_Wo_lo[DD*DD];    // [768][768]
__device__ __align__(256) __nv_bfloat16 g_W1_hi[FF*DD],  g_W1_lo[FF*DD];    // [3072][768]
__device__ __align__(256) __nv_bfloat16 g_W2_hi[DD*FF],  g_W2_lo[DD*FF];    // [768][3072]

// ================= PTX helpers (baseline ISA only: sm_80-class) =============
__device__ __forceinline__ uint32_t smem_u32(const void* p) {
    uint32_t a;
    asm("{ .reg .u64 t; cvta.to.shared.u64 t, %1; cvt.u32.u64 %0, t; }" : "=r"(a) : "l"(p));
    return a;
}
#define CP16(dst, src) asm volatile("cp.async.cg.shared.global [%0], [%1], 16;" :: "r"(dst), "l"(src))
#define CP_COMMIT()    asm volatile("cp.async.commit_group;" ::: "memory")
#define CP_WAIT(n)     asm volatile("cp.async.wait_group %0;" :: "n"(n) : "memory")

#define LDM4(r, addr) \
    asm volatile("ldmatrix.sync.aligned.m8n8.x4.shared.b16 {%0,%1,%2,%3}, [%4];" \
        : "=r"((r)[0]), "=r"((r)[1]), "=r"((r)[2]), "=r"((r)[3]) : "r"(addr))
#define LDM4T(r, addr) \
    asm volatile("ldmatrix.sync.aligned.m8n8.x4.trans.shared.b16 {%0,%1,%2,%3}, [%4];" \
        : "=r"((r)[0]), "=r"((r)[1]), "=r"((r)[2]), "=r"((r)[3]) : "r"(addr))

#define MMA16816(d, a, b0v, b1v) \
    asm volatile("mma.sync.aligned.m16n8k16.row.col.f32.bf16.bf16.f32 " \
        "{%0,%1,%2,%3},{%4,%5,%6,%7},{%8,%9},{%0,%1,%2,%3};" \
        : "+f"((d)[0]), "+f"((d)[1]), "+f"((d)[2]), "+f"((d)[3]) \
        : "r"((a)[0]), "r"((a)[1]), "r"((a)[2]), "r"((a)[3]), "r"(b0v), "r"(b1v))

__device__ __forceinline__ void split_bf16(float v, __nv_bfloat16& hi, __nv_bfloat16& lo) {
    hi = __float2bfloat16(v);
    lo = __float2bfloat16(v - __bfloat162float(hi));
}
__device__ __forceinline__ uint32_t pack_bf2(float a, float b) {
    __nv_bfloat162 t = __halves2bfloat162(__float2bfloat16(a), __float2bfloat16(b));
    return *(uint32_t*)&t;
}
__device__ __forceinline__ float gelu_exact(float x) {
    return 0.5f * x * (1.0f + erff(x * 0.70710678118654752f));
}

// ================= weight conversion (coalesced transposes) =================
// W[K][N] fp32 -> O[N][K] split bf16, 32x32 smem tiles.
__global__ void tcvt_t(const float* __restrict__ W, __nv_bfloat16* __restrict__ Ohi,
                       __nv_bfloat16* __restrict__ Olo, int K, int N)
{
    __shared__ float t[32][33];
    int n0 = blockIdx.x * 32, k0 = blockIdx.y * 32;
    int tx = threadIdx.x, ty = threadIdx.y;
    #pragma unroll
    for (int j = 0; j < 4; j++)
        t[ty + 8 * j][tx] = W[(size_t)(k0 + ty + 8 * j) * N + n0 + tx];
    __syncthreads();
    #pragma unroll
    for (int j = 0; j < 4; j++) {
        int n = n0 + ty + 8 * j;
        float v = t[tx][ty + 8 * j];
        __nv_bfloat16 hi, lo; split_bf16(v, hi, lo);
        Ohi[(size_t)n * K + k0 + tx] = hi;
        Olo[(size_t)n * K + k0 + tx] = lo;
    }
}
// Wq/Wk/Wv [H][D][HD] -> g_Wqkv[(part*768+h*64+e)][d], transposed per (part,h).
// Bias fused: the d0==0 block also packs bq/bk/bv into g_bp.
__global__ void qkv_cvt_t(const float* __restrict__ Wq, const float* __restrict__ Wk,
                          const float* __restrict__ Wv, const float* __restrict__ bq,
                          const float* __restrict__ bk, const float* __restrict__ bv)
{
    __shared__ float t[32][33];
    int d0 = blockIdx.x * 32, e0 = blockIdx.y * 32;
    int part = blockIdx.z / HH, h = blockIdx.z % HH;
    const float* W = (part == 0) ? Wq : (part == 1) ? Wk : Wv;
    int tx = threadIdx.x, ty = threadIdx.y;
    #pragma unroll
    for (int j = 0; j < 4; j++)
        t[ty + 8 * j][tx] = W[(size_t)(h * DD + d0 + ty + 8 * j) * HDD + e0 + tx];
    if (d0 == 0 && ty == 0) {
        const float* bb = (part == 0) ? bq : (part == 1) ? bk : bv;
        int e = e0 + tx;
        g_bp[part * DD + h * HDD + e] = bb[h * HDD + e];
    }
    __syncthreads();
    #pragma unroll
    for (int j = 0; j < 4; j++) {
        int e = e0 + ty + 8 * j;
        int row = part * DD + h * HDD + e;
        float v = t[tx][ty + 8 * j];
        __nv_bfloat16 hi, lo; split_bf16(v, hi, lo);
        g_Wqkv_hi[(size_t)row * DD + d0 + tx] = hi;
        g_Wqkv_lo[(size_t)row * DD + d0 + tx] = lo;
    }
}

// ================= layer norm (writes split bf16) =================
__global__ void ln_kernel(const float* __restrict__ x, const float* __restrict__ g,
                          const float* __restrict__ b, __nv_bfloat16* __restrict__ yhi,
                          __nv_bfloat16* __restrict__ ylo)
{
    int row = blockIdx.x;
    int tid = threadIdx.x;
    const float* xr = x + (size_t)row * DD;
    float v0 = xr[tid], v1 = xr[tid + 256], v2 = xr[tid + 512];
    float s  = v0 + v1 + v2;
    float ss = v0 * v0 + v1 * v1 + v2 * v2;
    #pragma unroll
    for (int o = 16; o >= 1; o >>= 1) {
        s  += __shfl_xor_sync(0xffffffffu, s,  o);
        ss += __shfl_xor_sync(0xffffffffu, ss, o);
    }
    __shared__ float rs[8], rss[8];
    int w = tid >> 5, l = tid & 31;
    if (l == 0) { rs[w] = s; rss[w] = ss; }
    __syncthreads();
    float S = 0.f, S2 = 0.f;
    #pragma unroll
    for (int i = 0; i < 8; i++) { S += rs[i]; S2 += rss[i]; }
    float mu  = S  * (1.0f / DD);
    float var = S2 * (1.0f / DD) - mu * mu;
    float inv = rsqrtf(var + 1e-5f);
    #pragma unroll
    for (int q = 0; q < 3; q++) {
        int c = tid + q * 256;
        float v = (q == 0 ? v0 : q == 1 ? v1 : v2);
        float y = (v - mu) * inv * g[c] + b[c];
        __nv_bfloat16 hi, lo; split_bf16(y, hi, lo);
        yhi[(size_t)row * DD + c] = hi;
        ylo[(size_t)row * DD + c] = lo;
    }
}

// LN2 fused over 3 split-K partials + bias (a = sum + bo; y = LN(a) -> split)
__global__ void ln2_fuse(const float* __restrict__ bo, const float* __restrict__ g,
                         const float* __restrict__ b, __nv_bfloat16* __restrict__ yhi,
                         __nv_bfloat16* __restrict__ ylo)
{
    const size_t plane = (size_t)ROWS * DD;
    int row = blockIdx.x;
    int tid = threadIdx.x;
    const float* p = g_part + (size_t)row * DD;
    float v[3];
    #pragma unroll
    for (int q = 0; q < 3; q++) {
        int c = tid + q * 256;
        v[q] = p[c] + p[plane + c] + p[2 * plane + c] + bo[c];
    }
    float s  = v[0] + v[1] + v[2];
    float ss = v[0]*v[0] + v[1]*v[1] + v[2]*v[2];
    #pragma unroll
    for (int o = 16; o >= 1; o >>= 1) {
        s  += __shfl_xor_sync(0xffffffffu, s,  o);
        ss += __shfl_xor_sync(0xffffffffu, ss, o);
    }
    __shared__ float rs[8], rss[8];
    int w = tid >> 5, l = tid & 31;
    if (l == 0) { rs[w] = s; rss[w] = ss; }
    __syncthreads();
    float S = 0.f, S2 = 0.f;
    #pragma unroll
    for (int i = 0; i < 8; i++) { S += rs[i]; S2 += rss[i]; }
    float mu  = S  * (1.0f / DD);
    float var = S2 * (1.0f / DD) - mu * mu;
    float inv = rsqrtf(var + 1e-5f);
    #pragma unroll
    for (int q = 0; q < 3; q++) {
        int c = tid + q * 256;
        float y = (v[q] - mu) * inv * g[c] + b[c];
        __nv_bfloat16 hi, lo; split_bf16(y, hi, lo);
        yhi[(size_t)row * DD + c] = hi;
        ylo[(size_t)row * DD + c] = lo;
    }
}

// out = p0 + p1 + p2 + bias (FFN2 reduce)
__global__ void addbias3(const float* __restrict__ bias, float* __restrict__ out)
{
    const size_t plane = (size_t)ROWS * DD;
    size_t i4 = ((size_t)blockIdx.x * 256 + threadIdx.x) * 4;
    if (i4 >= plane) return;
    int c = (int)(i4 % DD);
    float4 a = *(const float4*)(g_part + i4);
    float4 b = *(const float4*)(g_part + plane + i4);
    float4 d = *(const float4*)(g_part + 2 * plane + i4);
    float4 bb = *(const float4*)(bias + c);
    float4 r;
    r.x = a.x + b.x + d.x + bb.x;
    r.y = a.y + b.y + d.y + bb.y;
    r.z = a.z + b.z + d.z + bb.z;
    r.w = a.w + b.w + d.w + bb.w;
    *(float4*)(out + i4) = r;
}

// ================ mma.sync GEMM: C[M,N] = A[M,K] @ Bt[N,K]^T ================
// R12 champion config: 8 warps (4x2), 32x64 warp tile, 256 threads, 2 CTAs/SM,
// single-barrier 3-stage pipeline with loads issued before compute.
#define STAGE_B  32768
#define GEMM_SMEM (3*STAGE_B)

template<int ACT, int OSPLIT, int PART>
__global__ __launch_bounds__(256, 2)
void tgemm(const __nv_bfloat16* __restrict__ Ahi, const __nv_bfloat16* __restrict__ Alo,
           const __nv_bfloat16* __restrict__ Bhi, const __nv_bfloat16* __restrict__ Blo,
           const float* __restrict__ bias,
           float* __restrict__ Cf, __nv_bfloat16* __restrict__ Chi,
           __nv_bfloat16* __restrict__ Clo, int N, int K)
{
    extern __shared__ char smem[];
    uint32_t ST = smem_u32(smem);
    int tid = threadIdx.x;
    int lane = tid & 31, wid = tid >> 5;
    int wr = wid & 3, wc = wid >> 2;          // warp grid 4 x 2
    int m0 = blockIdx.y * 128;
    int n0 = blockIdx.x * 128;
    int KH = PART ? (K / (int)gridDim.z) : K;
    int koff = PART ? ((int)blockIdx.z * KH) : 0;
    int nc = KH >> 5;                          // K chunks of 32

    const __nv_bfloat16* Abase_h = Ahi + (size_t)m0 * K + koff;
    const __nv_bfloat16* Abase_l = Alo + (size_t)m0 * K + koff;
    const __nv_bfloat16* Bbase_h = Bhi + (size_t)n0 * K + koff;
    const __nv_bfloat16* Bbase_l = Blo + (size_t)n0 * K + koff;

    auto load_chunk = [&](int c, int p) {
        uint32_t base = ST + p * STAGE_B;
        const __nv_bfloat16* ah = Abase_h + c * 32;
        const __nv_bfloat16* al = Abase_l + c * 32;
        const __nv_bfloat16* bh = Bbase_h + c * 32;
        const __nv_bfloat16* bl = Bbase_l + c * 32;
        #pragma unroll
        for (int j = 0; j < 2; j++) {
            int id = tid + 256 * j;            // 0..511 : 128 rows x 4 chunks
            int r = id >> 2, cc = id & 3;
            uint32_t off = (uint32_t)(r * 64 + ((cc ^ ((r >> 1) & 3)) << 4));
            const size_t go = (size_t)r * K + cc * 8;
            CP16(base +         off, ah + go);
            CP16(base +  8192 + off, al + go);
            CP16(base + 16384 + off, bh + go);
            CP16(base + 24576 + off, bl + go);
        }
    };

    float acc[2][8][4];
    #pragma unroll
    for (int s = 0; s < 2; s++)
        #pragma unroll
        for (int t = 0; t < 8; t++)
            #pragma unroll
            for (int q = 0; q < 4; q++) acc[s][t][q] = 0.f;

    load_chunk(0, 0); CP_COMMIT();
    load_chunk(1, 1); CP_COMMIT();

    int arow = wr * 32 + (lane & 15);
    int brow = wc * 64 + (lane & 15);
    int khalf = lane >> 4;

    for (int c = 0; c < nc; c++) {
        CP_WAIT(1);                 // chunk c landed (next group may be in flight)
        __syncthreads();            // all warps past iter c-1 (stage (c+2)%3 free)
        if (c + 2 < nc) load_chunk(c + 2, (c + 2) % 3);
        CP_COMMIT();                // empty when skipped: uniform group count
        uint32_t base = ST + (c % 3) * STAGE_B;
        uint32_t Ah = base, Al = base + 8192, Bh = base + 16384, Bl = base + 24576;
        #pragma unroll
        for (int ks = 0; ks < 2; ks++) {
            uint32_t ahf[2][4], alf[2][4];
            #pragma unroll
            for (int sub = 0; sub < 2; sub++) {
                int r = arow + sub * 16;
                int kc = ks * 2 + khalf;
                uint32_t off = (uint32_t)(r * 64 + ((kc ^ ((r >> 1) & 3)) << 4));
                LDM4(ahf[sub], Ah + off);
                LDM4(alf[sub], Al + off);
            }
            #pragma unroll
            for (int nh = 0; nh < 4; nh++) {
                int n = brow + nh * 16;
                int kc = ks * 2 + khalf;
                uint32_t off = (uint32_t)(n * 64 + ((kc ^ ((n >> 1) & 3)) << 4));
                uint32_t bhf[4], blf[4];
                LDM4(bhf, Bh + off);
                LDM4(blf, Bl + off);
                #pragma unroll
                for (int sub = 0; sub < 2; sub++) {
                    #pragma unroll
                    for (int nt = 0; nt < 2; nt++) {
                        float* d = acc[sub][nh * 2 + nt];
                        MMA16816(d, ahf[sub], bhf[nt], bhf[nt + 2]);
                        MMA16816(d, ahf[sub], blf[nt], blf[nt + 2]);
                        MMA16816(d, alf[sub], bhf[nt], bhf[nt + 2]);
                    }
                }
            }
        }
    }

    // ---------------- epilogue ----------------
    float* Cpart = PART ? (Cf + (size_t)blockIdx.z * ROWS * N) : Cf;
    int g = lane >> 2, t = lane & 3;
    #pragma unroll
    for (int sub = 0; sub < 2; sub++) {
        #pragma unroll
        for (int nt8 = 0; nt8 < 8; nt8++) {
            int col = n0 + wc * 64 + nt8 * 8 + t * 2;
            float b0 = PART ? 0.f : bias[col];
            float b1 = PART ? 0.f : bias[col + 1];
            #pragma unroll
            for (int half = 0; half < 2; half++) {
                int row = m0 + wr * 32 + sub * 16 + g + half * 8;
                float v0 = acc[sub][nt8][half * 2 + 0] + b0;
                float v1 = acc[sub][nt8][half * 2 + 1] + b1;
                if (ACT) { v0 = gelu_exact(v0); v1 = gelu_exact(v1); }
                if (OSPLIT) {
                    __nv_bfloat16 h0, l0, h1, l1;
                    split_bf16(v0, h0, l0); split_bf16(v1, h1, l1);
                    *(__nv_bfloat162*)(Chi + (size_t)row * N + col) = __halves2bfloat162(h0, h1);
                    *(__nv_bfloat162*)(Clo + (size_t)row * N + col) = __halves2bfloat162(l0, l1);
                } else {
                    float2 fv; fv.x = v0; fv.y = v1;
                    *(float2*)(Cpart + (size_t)row * N + col) = fv;
                }
            }
        }
    }
}

// ============ tensor-core flash attention (bf16 split, 64x64 tiles) =========
// R12 champion config: 64-row Q tile, 128 threads, 2 CTAs/SM, 3-stage KV
// pipeline with loads issued before compute, Q read via ldmatrix per iter
// (register-pressure-friendly; the hoisted variant measured slower in R14).
#define ATT_STAGE 32768
#define ATT_SMEM  (16384 + 3*ATT_STAGE)

__device__ __forceinline__ uint32_t aoff(int r, int c) {
    return (uint32_t)((r << 7) + (((c ^ (r & 7)) & 7) << 4));
}

__global__ __launch_bounds__(128, 2)
void attn_tc(const __nv_bfloat16* __restrict__ qh, const __nv_bfloat16* __restrict__ ql,
             __nv_bfloat16* __restrict__ ohi, __nv_bfloat16* __restrict__ olo)
{
    extern __shared__ char sm[];
    uint32_t S0 = smem_u32(sm);
    const uint32_t Qh = S0, Ql = S0 + 8192;
    int tid = threadIdx.x, lane = tid & 31, wid = tid >> 5;
    int bh = blockIdx.y, b = bh / HH, h = bh - b * HH;
    int q0 = blockIdx.x * 64;
    size_t rowbase = (size_t)b * SS * NC + h * 64;
    const int NT = SS / 64;

    {
        const __nv_bfloat16* qph = qh + rowbase + (size_t)q0 * NC;
        const __nv_bfloat16* qpl = ql + rowbase + (size_t)q0 * NC;
        #pragma unroll
        for (int j = 0; j < 4; j++) {
            int id = tid + 128 * j; int r = id >> 3, c = id & 7;
            size_t go = (size_t)r * NC + c * 8;
            CP16(Qh + aoff(r, c), qph + go);
            CP16(Ql + aoff(r, c), qpl + go);
        }
        CP_COMMIT();
    }
    auto load_kv = [&](int kt, int p) {
        uint32_t base = S0 + 16384 + p * ATT_STAGE;
        size_t kb = rowbase + (size_t)(kt * 64) * NC + 768;
        size_t vb = kb + 768;
        #pragma unroll
        for (int j = 0; j < 4; j++) {
            int id = tid + 128 * j; int r = id >> 3, c = id & 7;
            uint32_t o_ = aoff(r, c);
            size_t go = (size_t)r * NC + c * 8;
            CP16(base +         o_, qh + kb + go);
            CP16(base +  8192 + o_, ql + kb + go);
            CP16(base + 16384 + o_, qh + vb + go);
            CP16(base + 24576 + o_, ql + vb + go);
        }
    };
    load_kv(0, 0); CP_COMMIT();
    load_kv(1, 1); CP_COMMIT();

    float o[8][4];
    #pragma unroll
    for (int i = 0; i < 8; i++)
        #pragma unroll
        for (int q = 0; q < 4; q++) o[i][q] = 0.f;
    float m0r = -1e30f, m1r = -1e30f, l0r = 0.f, l1r = 0.f;
    int g = lane >> 2, t = lane & 3;
    int arow = wid * 16 + (lane & 15);
    int khalf = lane >> 4;

    for (int kt = 0; kt < NT; kt++) {
        int p = kt % 3;
        CP_WAIT(1);                 // stage kt landed (1 newer group in flight)
        __syncthreads();            // all warps past iter kt-1 (stage (kt+2)%3 free)
        if (kt + 2 < NT) load_kv(kt + 2, (kt + 2) % 3);
        CP_COMMIT();                // empty when skipped: uniform group count
        uint32_t base = S0 + 16384 + p * ATT_STAGE;
        uint32_t Kh = base, Kl = base + 8192, Vh = base + 16384, Vl = base + 24576;

        float s[8][4];
        #pragma unroll
        for (int i = 0; i < 8; i++)
            #pragma unroll
            for (int q = 0; q < 4; q++) s[i][q] = 0.f;
        #pragma unroll
        for (int ks = 0; ks < 4; ks++) {
            uint32_t qah[4], qal[4];
            uint32_t ao = aoff(arow, ks * 2 + khalf);
            LDM4(qah, Qh + ao);
            LDM4(qal, Ql + ao);
            #pragma unroll
            for (int np = 0; np < 4; np++) {
                uint32_t bo = aoff(np * 16 + (lane & 15), ks * 2 + khalf);
                uint32_t kbh[4], kbl[4];
                LDM4(kbh, Kh + bo);
                LDM4(kbl, Kl + bo);
                #pragma unroll
                for (int half = 0; half < 2; half++) {
                    float* d = s[np * 2 + half];
                    MMA16816(d, qah, kbh[half], kbh[half + 2]);
                    MMA16816(d, qah, kbl[half], kbl[half + 2]);
                    MMA16816(d, qal, kbh[half], kbh[half + 2]);
                }
            }
        }
        float mn0 = m0r, mn1 = m1r;
        #pragma unroll
        for (int nb = 0; nb < 8; nb++) {
            s[nb][0] *= 0.125f; s[nb][1] *= 0.125f;
            s[nb][2] *= 0.125f; s[nb][3] *= 0.125f;
            mn0 = fmaxf(mn0, fmaxf(s[nb][0], s[nb][1]));
            mn1 = fmaxf(mn1, fmaxf(s[nb][2], s[nb][3]));
        }
        mn0 = fmaxf(mn0, __shfl_xor_sync(0xffffffffu, mn0, 1));
        mn0 = fmaxf(mn0, __shfl_xor_sync(0xffffffffu, mn0, 2));
        mn1 = fmaxf(mn1, __shfl_xor_sync(0xffffffffu, mn1, 1));
        mn1 = fmaxf(mn1, __shfl_xor_sync(0xffffffffu, mn1, 2));
        float al0 = __expf(m0r - mn0), al1 = __expf(m1r - mn1);
        m0r = mn0; m1r = mn1;
        float sum0 = 0.f, sum1 = 0.f;
        uint32_t ph[4][4], pl[4][4];
        #pragma unroll
        for (int kg = 0; kg < 4; kg++) {
            #pragma unroll
            for (int half = 0; half < 2; half++) {
                int nb = kg * 2 + half;
                float p0 = __expf(s[nb][0] - mn0), p1 = __expf(s[nb][1] - mn0);
                float p2 = __expf(s[nb][2] - mn1), p3 = __expf(s[nb][3] - mn1);
                sum0 += p0 + p1; sum1 += p2 + p3;
                float h0 = __bfloat162float(__float2bfloat16(p0));
                float h1 = __bfloat162float(__float2bfloat16(p1));
                float h2 = __bfloat162float(__float2bfloat16(p2));
                float h3 = __bfloat162float(__float2bfloat16(p3));
                ph[kg][half * 2 + 0] = pack_bf2(p0, p1);
                ph[kg][half * 2 + 1] = pack_bf2(p2, p3);
                pl[kg][half * 2 + 0] = pack_bf2(p0 - h0, p1 - h1);
                pl[kg][half * 2 + 1] = pack_bf2(p2 - h2, p3 - h3);
            }
        }
        l0r = l0r * al0 + sum0;
        l1r = l1r * al1 + sum1;
        #pragma unroll
        for (int nb = 0; nb < 8; nb++) {
            o[nb][0] *= al0; o[nb][1] *= al0;
            o[nb][2] *= al1; o[nb][3] *= al1;
        }
        #pragma unroll
        for (int kg = 0; kg < 4; kg++) {
            #pragma unroll
            for (int ep = 0; ep < 4; ep++) {
                uint32_t vo = aoff(kg * 16 + (lane & 15), ep * 2 + khalf);
                uint32_t vbh[4], vbl[4];
                LDM4T(vbh, Vh + vo);
                LDM4T(vbl, Vl + vo);
                #pragma unroll
                for (int half = 0; half < 2; half++) {
                    float* d = o[ep * 2 + half];
                    MMA16816(d, ph[kg], vbh[half * 2], vbh[half * 2 + 1]);
                    MMA16816(d, ph[kg], vbl[half * 2], vbl[half * 2 + 1]);
                    MMA16816(d, pl[kg], vbh[half * 2], vbh[half * 2 + 1]);
                }
            }
        }
    }
    l0r += __shfl_xor_sync(0xffffffffu, l0r, 1);
    l0r += __shfl_xor_sync(0xffffffffu, l0r, 2);
    l1r += __shfl_xor_sync(0xffffffffu, l1r, 1);
    l1r += __shfl_xor_sync(0xffffffffu, l1r, 2);
    float inv0 = 1.f / l0r, inv1 = 1.f / l1r;
    int r0 = q0 + wid * 16 + g, r1 = r0 + 8;
    #pragma unroll
    for (int eb = 0; eb < 8; eb++) {
        int col = h * 64 + eb * 8 + t * 2;
        size_t o0 = (size_t)(b * SS + r0) * DD + col;
        size_t o1 = (size_t)(b * SS + r1) * DD + col;
        float v00 = o[eb][0] * inv0, v01 = o[eb][1] * inv0;
        float v10 = o[eb][2] * inv1, v11 = o[eb][3] * inv1;
        __nv_bfloat16 h0, l0, h1, l1, h2, l2, h3, l3;
        split_bf16(v00, h0, l0); split_bf16(v01, h1, l1);
        split_bf16(v10, h2, l2); split_bf16(v11, h3, l3);
        *(__nv_bfloat162*)(ohi + o0) = __halves2bfloat162(h0, h1);
        *(__nv_bfloat162*)(olo + o0) = __halves2bfloat162(l0, l1);
        *(__nv_bfloat162*)(ohi + o1) = __halves2bfloat162(h2, h3);
        *(__nv_bfloat162*)(olo + o1) = __halves2bfloat162(l2, l3);
    }
}

// ================= launch =================
extern "C" void kernel_launch(void* const* d_in, const int* in_sizes, int n_in,
                              void* d_out, int out_size)
{
    const float* x   = (const float*)d_in[0];
    const float* Wq  = (const float*)d_in[1];
    const float* bq  = (const float*)d_in[2];
    const float* Wk  = (const float*)d_in[3];
    const float* bk  = (const float*)d_in[4];
    const float* Wv  = (const float*)d_in[5];
    const float* bv  = (const float*)d_in[6];
    const float* Wo  = (const float*)d_in[7];
    const float* bo  = (const float*)d_in[8];
    const float* W1  = (const float*)d_in[9];
    const float* b1  = (const float*)d_in[10];
    const float* W2  = (const float*)d_in[11];
    const float* b2  = (const float*)d_in[12];
    const float* g1  = (const float*)d_in[13];
    const float* be1 = (const float*)d_in[14];
    const float* g2  = (const float*)d_in[15];
    const float* be2 = (const float*)d_in[16];
    float* out = (float*)d_out;

    void *ppart, *pbp, *phh, *phl, *pqh, *pql, *poh, *pol, *pfh, *pfl;
    void *pWoh, *pWol, *pW1h, *pW1l, *pW2h, *pW2l, *pWqh, *pWql;
    cudaGetSymbolAddress(&ppart, g_part);
    cudaGetSymbolAddress(&pbp,  g_bp);
    cudaGetSymbolAddress(&phh,  g_h_hi);  cudaGetSymbolAddress(&phl, g_h_lo);
    cudaGetSymbolAddress(&pqh,  g_qkvh);  cudaGetSymbolAddress(&pql, g_qkvl);
    cudaGetSymbolAddress(&poh,  g_o_hi);  cudaGetSymbolAddress(&pol, g_o_lo);
    cudaGetSymbolAddress(&pfh,  g_f_hi);  cudaGetSymbolAddress(&pfl, g_f_lo);
    cudaGetSymbolAddress(&pWqh, g_Wqkv_hi); cudaGetSymbolAddress(&pWql, g_Wqkv_lo);
    cudaGetSymbolAddress(&pWoh, g_Wo_hi);   cudaGetSymbolAddress(&pWol, g_Wo_lo);
    cudaGetSymbolAddress(&pW1h, g_W1_hi);   cudaGetSymbolAddress(&pW1l, g_W1_lo);
    cudaGetSymbolAddress(&pW2h, g_W2_hi);   cudaGetSymbolAddress(&pW2l, g_W2_lo);
    float* part = (float*)ppart;
    float* bp   = (float*)pbp;
    __nv_bfloat16* hh = (__nv_bfloat16*)phh, *hl = (__nv_bfloat16*)phl;
    __nv_bfloat16* qvh = (__nv_bfloat16*)pqh, *qvl = (__nv_bfloat16*)pql;
    __nv_bfloat16* oh = (__nv_bfloat16*)poh, *ol = (__nv_bfloat16*)pol;
    __nv_bfloat16* fh = (__nv_bfloat16*)pfh, *fl = (__nv_bfloat16*)pfl;
    __nv_bfloat16* Wqh = (__nv_bfloat16*)pWqh, *Wql = (__nv_bfloat16*)pWql;
    __nv_bfloat16* Woh = (__nv_bfloat16*)pWoh, *Wol = (__nv_bfloat16*)pWol;
    __nv_bfloat16* W1h = (__nv_bfloat16*)pW1h, *W1l = (__nv_bfloat16*)pW1l;
    __nv_bfloat16* W2h = (__nv_bfloat16*)pW2h, *W2l = (__nv_bfloat16*)pW2l;

    cudaFuncSetAttribute(tgemm<0,1,0>, cudaFuncAttributeMaxDynamicSharedMemorySize, GEMM_SMEM);
    cudaFuncSetAttribute(tgemm<0,0,1>, cudaFuncAttributeMaxDynamicSharedMemorySize, GEMM_SMEM);
    cudaFuncSetAttribute(tgemm<1,1,0>, cudaFuncAttributeMaxDynamicSharedMemorySize, GEMM_SMEM);
    cudaFuncSetAttribute(attn_tc,      cudaFuncAttributeMaxDynamicSharedMemorySize, ATT_SMEM);

    // weight prep (coalesced transposes; qkv bias fused)
    qkv_cvt_t<<<dim3(DD/32, HDD/32, 3*HH), dim3(32,8)>>>(Wq, Wk, Wv, bq, bk, bv);
    tcvt_t<<<dim3(DD/32, DD/32),  dim3(32,8)>>>(Wo, Woh, Wol, DD, DD);
    tcvt_t<<<dim3(FF/32, DD/32),  dim3(32,8)>>>(W1, W1h, W1l, DD, FF);
    tcvt_t<<<dim3(DD/32, FF/32),  dim3(32,8)>>>(W2, W2h, W2l, FF, DD);
    // LN1 -> split
    ln_kernel<<<ROWS, 256>>>(x, g1, be1, hh, hl);
    // QKV projection -> split bf16 qkv
    tgemm<0,1,0><<<dim3(NC/128, ROWS/128), 256, GEMM_SMEM>>>(
        hh, hl, Wqh, Wql, bp, nullptr, qvh, qvl, NC, DD);
    // tensor-core flash attention (64-row Q tile, 2 CTAs/SM) -> split bf16 o
    attn_tc<<<dim3(SS/64, BB*HH), 128, ATT_SMEM>>>(qvh, qvl, oh, ol);
    // output projection: split-K=3 partials
    tgemm<0,0,1><<<dim3(DD/128, ROWS/128, 3), 256, GEMM_SMEM>>>(
        oh, ol, Woh, Wol, nullptr, part, nullptr, nullptr, DD, DD);
    // fused reduce + bias + LN2 -> split
    ln2_fuse<<<ROWS, 256>>>(bo, g2, be2, hh, hl);
    // FFN up + GELU -> split
    tgemm<1,1,0><<<dim3(FF/128, ROWS/128), 256, GEMM_SMEM>>>(
        hh, hl, W1h, W1l, b1, nullptr, fh, fl, FF, DD);
    // FFN down: split-K=3 partials
    tgemm<0,0,1><<<dim3(DD/128, ROWS/128, 3), 256, GEMM_SMEM>>>(
        fh, fl, W2h, W2l, nullptr, part, nullptr, nullptr, DD, FF);
    // reduce + bias -> output
    addbias3<<<(ROWS*DD/4 + 255)/256, 256>>>(b2, out);
}